// round 15
// baseline (speedup 1.0000x reference)
#include <cuda_runtime.h>
#include <cuda_fp16.h>
#include <mma.h>
#include <cstdint>

using namespace nvcuda;

// Problem constants
#define Bc   8
#define Nn   4096
#define DIM  1536
#define Hh   24
#define HD   64
#define Rr   8
#define JH   192
#define SCALE 0.125f
#define MASKW (Nn - Rr)

#define KSPY 2                  // split-K for Y (2048 per split)

// ---------------- scratch ----------------
__device__ __half g_Gh[Bc * JH * DIM];                  // [b][j][c] half
__device__ __half g_xh[(size_t)Bc * Nn * DIM];          // half copy of x
__device__ float  g_Sf[(size_t)Bc * JH * Nn];           // logits (fp32)
__device__ __half g_Sh[(size_t)Bc * JH * Nn];           // probs (half)
__device__ float  g_Yp[KSPY][Bc * JH * DIM];            // partial Y (fp32)
__device__ float  g_xcls[Bc * Rr * DIM];

// ---------------- cp.async helpers ----------------
__device__ __forceinline__ void cp16(void* s, const void* g) {
    uint32_t sa = (uint32_t)__cvta_generic_to_shared(s);
    asm volatile("cp.async.ca.shared.global [%0], [%1], 16;" :: "r"(sa), "l"(g));
}
__device__ __forceinline__ void cp_commit() { asm volatile("cp.async.commit_group;"); }
template<int N> __device__ __forceinline__ void cp_wait() {
    asm volatile("cp.async.wait_group %0;" :: "n"(N));
}

// ============================================================================
// K0: g_xh = half(x)  — vectorized convert, 8 floats/thread, no smem
// ============================================================================
__global__ void __launch_bounds__(256) k_xh(const float* __restrict__ x) {
    size_t i = ((size_t)blockIdx.x * 256 + threadIdx.x) * 8;
    float4 v0 = *(const float4*)&x[i];
    float4 v1 = *(const float4*)&x[i + 4];
    __half2 h[4];
    h[0] = __floats2half2_rn(v0.x, v0.y);
    h[1] = __floats2half2_rn(v0.z, v0.w);
    h[2] = __floats2half2_rn(v1.x, v1.y);
    h[3] = __floats2half2_rn(v1.z, v1.w);
    *(uint4*)&g_xh[i] = *(uint4*)h;
}

// ============================================================================
// K1 (fused): q = SCALE * x[:8] @ Wq_h^T ; G[j] = half(q @ Wk_h)
// grid 192 = (b,h), 256 threads
// ============================================================================
__global__ void __launch_bounds__(256) k_qg(const float* __restrict__ x,
                                            const float* __restrict__ Wq,
                                            const float* __restrict__ Wk) {
    int b = blockIdx.x / Hh, h = blockIdx.x % Hh;
    __shared__ float xs[Rr * DIM];
    const float* xb = x + (size_t)b * Nn * DIM;
    for (int i = threadIdx.x; i < Rr * DIM; i += 256) xs[i] = xb[i];
    __syncthreads();
    int warp = threadIdx.x >> 5, lane = threadIdx.x & 31;

    float qv[8];
    #pragma unroll 1
    for (int i = 0; i < 8; i++) {
        int d = warp * 8 + i;
        const float* wrow = Wq + (size_t)(h * HD + d) * DIM;
        float acc[8] = {0.f,0.f,0.f,0.f,0.f,0.f,0.f,0.f};
        for (int c = lane; c < DIM; c += 32) {
            float w = wrow[c];
            #pragma unroll
            for (int r = 0; r < 8; r++) acc[r] += w * xs[r * DIM + c];
        }
        #pragma unroll
        for (int r = 0; r < 8; r++)
            #pragma unroll
            for (int off = 16; off > 0; off >>= 1)
                acc[r] += __shfl_xor_sync(0xffffffffu, acc[r], off);
        qv[i] = (lane < 8) ? acc[lane] * SCALE : 0.f;
    }
    __syncthreads();
    if (lane < 8) {
        #pragma unroll
        for (int i = 0; i < 8; i++) xs[lane * HD + warp * 8 + i] = qv[i];
    }
    __syncthreads();

    float acc[6][8];
    #pragma unroll
    for (int cc = 0; cc < 6; cc++)
        #pragma unroll
        for (int r = 0; r < 8; r++) acc[cc][r] = 0.f;
    const float* wbase = Wk + (size_t)(h * HD) * DIM;
    #pragma unroll 4
    for (int d = 0; d < HD; d++) {
        #pragma unroll
        for (int cc = 0; cc < 6; cc++) {
            int c = cc * 256 + threadIdx.x;
            float w = wbase[(size_t)d * DIM + c];
            #pragma unroll
            for (int r = 0; r < 8; r++) acc[cc][r] += xs[r * HD + d] * w;
        }
    }
    #pragma unroll
    for (int cc = 0; cc < 6; cc++)
        #pragma unroll
        for (int r = 0; r < 8; r++)
            g_Gh[((size_t)b * JH + h * Rr + r) * DIM + cc * 256 + threadIdx.x] =
                __float2half_rn(acc[cc][r]);
}

// ============================================================================
// K2: S = Gh @ xh^T   (fp16 wmma m16n16k16)
// CTA 64(j) x 256(n), k-chunk 64, 2-stage cp.async. 8 warps 2x4, warp 32x64.
// grid (16, 3, Bc), 256 threads, dynamic smem 92KB
// ============================================================================
#define LD64  72                           // halves per k-chunk row (64 + 8 pad)
#define SA3   (64 * LD64)                  // 4608 halves / stage
#define SBS3  (256 * LD64)                 // 18432 halves / stage
#define SMEM_S ((SA3 + SBS3) * 2 * 2)      // 92160 B
#define NCS3  (DIM / 64)                   // 24 chunks
__global__ void __launch_bounds__(256) k_gemmS(int dummy) {
    extern __shared__ __half sm[];
    __half* As = sm;                        // 2 stages
    __half* Bs = sm + 2 * SA3;
    int b = blockIdx.z;
    int j0 = blockIdx.y * 64, n0 = blockIdx.x * 256;
    const __half* Ag = g_Gh + ((size_t)b * JH + j0) * DIM;
    const __half* Bg = g_xh + ((size_t)b * Nn + n0) * DIM;
    int tid = threadIdx.x;
    int warp = tid >> 5, wm = warp >> 2, wn = warp & 3;

    wmma::fragment<wmma::matrix_a, 16, 16, 16, __half, wmma::row_major> a0, a1;
    wmma::fragment<wmma::matrix_b, 16, 16, 16, __half, wmma::col_major> bf[4];
    wmma::fragment<wmma::accumulator, 16, 16, 16, float> c[2][4];
    #pragma unroll
    for (int mi = 0; mi < 2; mi++)
        #pragma unroll
        for (int ni = 0; ni < 4; ni++) wmma::fill_fragment(c[mi][ni], 0.f);

    auto prefetch = [&](int kc) {
        int s = kc & 1, k0 = kc << 6;
        #pragma unroll
        for (int p = 0; p < 2; p++) {
            int i = tid + p * 256; int row = i >> 3, seg = i & 7;
            cp16(&As[s * SA3 + row * LD64 + seg * 8], &Ag[(size_t)row * DIM + k0 + seg * 8]);
        }
        #pragma unroll
        for (int p = 0; p < 8; p++) {
            int i = tid + p * 256; int row = i >> 3, seg = i & 7;
            cp16(&Bs[s * SBS3 + row * LD64 + seg * 8], &Bg[(size_t)row * DIM + k0 + seg * 8]);
        }
        cp_commit();
    };
    prefetch(0);

    for (int kc = 0; kc < NCS3; kc++) {
        if (kc + 1 < NCS3) { prefetch(kc + 1); cp_wait<1>(); }
        else               { cp_wait<0>(); }
        __syncthreads();
        const __half* Ab = &As[(kc & 1) * SA3];
        const __half* Bb = &Bs[(kc & 1) * SBS3];
        #pragma unroll
        for (int kk = 0; kk < 64; kk += 16) {
            wmma::load_matrix_sync(a0, &Ab[(wm * 32) * LD64 + kk], LD64);
            wmma::load_matrix_sync(a1, &Ab[(wm * 32 + 16) * LD64 + kk], LD64);
            #pragma unroll
            for (int ni = 0; ni < 4; ni++)
                wmma::load_matrix_sync(bf[ni], &Bb[(wn * 64 + ni * 16) * LD64 + kk], LD64);
            #pragma unroll
            for (int ni = 0; ni < 4; ni++) {
                wmma::mma_sync(c[0][ni], a0, bf[ni], c[0][ni]);
                wmma::mma_sync(c[1][ni], a1, bf[ni], c[1][ni]);
            }
        }
        __syncthreads();
    }
    float* Sb = g_Sf + (size_t)b * JH * Nn;
    #pragma unroll
    for (int mi = 0; mi < 2; mi++)
        #pragma unroll
        for (int ni = 0; ni < 4; ni++)
            wmma::store_matrix_sync(&Sb[(size_t)(j0 + wm * 32 + mi * 16) * Nn + n0 + wn * 64 + ni * 16],
                                    c[mi][ni], Nn, wmma::mem_row_major);
}

// ============================================================================
// K3: masked softmax; writes half probs. grid 1536, 256 thr
// ============================================================================
__global__ void __launch_bounds__(256) k_softmax(const int* __restrict__ mask) {
    int bj = blockIdx.x;
    int b = bj / JH, j = bj % JH, r = j % Rr;
    const float* p0 = g_Sf + (size_t)bj * Nn;
    __half* row = g_Sh + (size_t)bj * Nn;
    const int* mrow = mask + ((size_t)b * Rr + r) * MASKW;
    int tid = threadIdx.x, warp = tid >> 5, lane = tid & 31;
    __shared__ float red[8];

    float v[16];
    float mx = -3.0e38f;
    #pragma unroll
    for (int i = 0; i < 16; i++) {
        int n = tid + (i << 8);
        bool valid = (n < Rr) ? (n == r) : (mrow[n - Rr] != 0);
        v[i] = valid ? p0[n] : -3.0e38f;
        mx = fmaxf(mx, v[i]);
    }
    #pragma unroll
    for (int off = 16; off > 0; off >>= 1) mx = fmaxf(mx, __shfl_xor_sync(0xffffffffu, mx, off));
    if (lane == 0) red[warp] = mx;
    __syncthreads();
    if (warp == 0) {
        float t = (lane < 8) ? red[lane] : -3.0e38f;
        #pragma unroll
        for (int off = 4; off > 0; off >>= 1) t = fmaxf(t, __shfl_xor_sync(0xffffffffu, t, off));
        if (lane == 0) red[0] = t;
    }
    __syncthreads();
    mx = red[0];
    __syncthreads();

    float sum = 0.f;
    #pragma unroll
    for (int i = 0; i < 16; i++) { v[i] = __expf(v[i] - mx); sum += v[i]; }
    #pragma unroll
    for (int off = 16; off > 0; off >>= 1) sum += __shfl_xor_sync(0xffffffffu, sum, off);
    if (lane == 0) red[warp] = sum;
    __syncthreads();
    if (warp == 0) {
        float t = (lane < 8) ? red[lane] : 0.f;
        #pragma unroll
        for (int off = 4; off > 0; off >>= 1) t += __shfl_xor_sync(0xffffffffu, t, off);
        if (lane == 0) red[0] = t;
    }
    __syncthreads();
    float inv = 1.f / red[0];
    #pragma unroll
    for (int i = 0; i < 16; i++)
        row[tid + (i << 8)] = __float2half_rn(v[i] * inv);
}

// ============================================================================
// K4: partial Y = Ph[:, slab] @ xh[slab, :]  (fp16 wmma m16n16k16, split-K 2)
// CTA 64(j) x 256(c), k-chunk 64, 2-stage cp.async. warp 32x64.
// grid (6, 3, Bc*KSPY), 256 threads, dynamic smem 86KB
// ============================================================================
#define LDBY3 264                          // halves per B row (256 + 8 pad)
#define SBY3  (64 * LDBY3)                 // 16896 halves / stage
#define SMEM_Y ((SA3 + SBY3) * 2 * 2)      // 86016 B
#define NCY3  (Nn / KSPY / 64)             // 32 chunks
__global__ void __launch_bounds__(256) k_gemmY(int dummy) {
    extern __shared__ __half sm[];
    __half* As = sm;
    __half* Bs = sm + 2 * SA3;
    int b = blockIdx.z >> 1, ks = blockIdx.z & 1;
    int koff = ks * (Nn / KSPY);
    int j0 = blockIdx.y * 64, c0 = blockIdx.x * 256;
    const __half* Ag = g_Sh + ((size_t)b * JH + j0) * Nn + koff;
    const __half* Bg = g_xh + ((size_t)b * Nn + koff) * DIM;
    int tid = threadIdx.x;
    int warp = tid >> 5, wm = warp >> 2, wn = warp & 3;

    wmma::fragment<wmma::matrix_a, 16, 16, 16, __half, wmma::row_major> a0, a1;
    wmma::fragment<wmma::matrix_b, 16, 16, 16, __half, wmma::row_major> bf[4];
    wmma::fragment<wmma::accumulator, 16, 16, 16, float> c[2][4];
    #pragma unroll
    for (int mi = 0; mi < 2; mi++)
        #pragma unroll
        for (int ni = 0; ni < 4; ni++) wmma::fill_fragment(c[mi][ni], 0.f);

    auto prefetch = [&](int kc) {
        int s = kc & 1, k0 = kc << 6;
        #pragma unroll
        for (int p = 0; p < 2; p++) {
            int i = tid + p * 256; int row = i >> 3, seg = i & 7;
            cp16(&As[s * SA3 + row * LD64 + seg * 8], &Ag[(size_t)row * Nn + k0 + seg * 8]);
        }
        #pragma unroll
        for (int p = 0; p < 8; p++) {
            int i = tid + p * 256; int row = i >> 5, seg = i & 31;
            cp16(&Bs[s * SBY3 + row * LDBY3 + seg * 8], &Bg[(size_t)(k0 + row) * DIM + c0 + seg * 8]);
        }
        cp_commit();
    };
    prefetch(0);

    for (int kc = 0; kc < NCY3; kc++) {
        if (kc + 1 < NCY3) { prefetch(kc + 1); cp_wait<1>(); }
        else               { cp_wait<0>(); }
        __syncthreads();
        const __half* Ab = &As[(kc & 1) * SA3];
        const __half* Bb = &Bs[(kc & 1) * SBY3];
        #pragma unroll
        for (int kk = 0; kk < 64; kk += 16) {
            wmma::load_matrix_sync(a0, &Ab[(wm * 32) * LD64 + kk], LD64);
            wmma::load_matrix_sync(a1, &Ab[(wm * 32 + 16) * LD64 + kk], LD64);
            #pragma unroll
            for (int ni = 0; ni < 4; ni++)
                wmma::load_matrix_sync(bf[ni], &Bb[kk * LDBY3 + wn * 64 + ni * 16], LDBY3);
            #pragma unroll
            for (int ni = 0; ni < 4; ni++) {
                wmma::mma_sync(c[0][ni], a0, bf[ni], c[0][ni]);
                wmma::mma_sync(c[1][ni], a1, bf[ni], c[1][ni]);
            }
        }
        __syncthreads();
    }
    float* Yb = g_Yp[ks] + (size_t)b * JH * DIM;
    #pragma unroll
    for (int mi = 0; mi < 2; mi++)
        #pragma unroll
        for (int ni = 0; ni < 4; ni++)
            wmma::store_matrix_sync(&Yb[(size_t)(j0 + wm * 32 + mi * 16) * DIM + c0 + wn * 64 + ni * 16],
                                    c[mi][ni], DIM, wmma::mem_row_major);
}

// ============================================================================
// K5a: reduce 2 Y partials + x_cls[b][r][e] = sum_c Y[b][h*8+r][c] * Wv[e][c]
// grid 768 = (b, h, equarter), 256 threads; each block does 16 e-values
// ============================================================================
__global__ void __launch_bounds__(256) k_xcls(const float* __restrict__ Wv) {
    int bh = blockIdx.x >> 2, eq = blockIdx.x & 3;
    int b = bh / Hh, h = bh % Hh;
    __shared__ float Ys[Rr * DIM];
    size_t base = ((size_t)b * JH + h * Rr) * DIM;
    for (int i = threadIdx.x; i < Rr * DIM; i += 256)
        Ys[i] = g_Yp[0][base + i] + g_Yp[1][base + i];
    __syncthreads();
    int warp = threadIdx.x >> 5, lane = threadIdx.x & 31;
    #pragma unroll 1
    for (int i = 0; i < 2; i++) {
        int e = h * HD + eq * 16 + warp * 2 + i;
        const float* wrow = Wv + (size_t)e * DIM;
        float acc[8] = {0.f,0.f,0.f,0.f,0.f,0.f,0.f,0.f};
        for (int c = lane; c < DIM; c += 32) {
            float w = wrow[c];
            #pragma unroll
            for (int r = 0; r < 8; r++) acc[r] += w * Ys[r * DIM + c];
        }
        #pragma unroll
        for (int r = 0; r < 8; r++)
            #pragma unroll
            for (int off = 16; off > 0; off >>= 1)
                acc[r] += __shfl_xor_sync(0xffffffffu, acc[r], off);
        if (lane < 8)
            g_xcls[((size_t)b * Rr + lane) * DIM + e] = acc[lane];
    }
}

// ============================================================================
// K5b: out[b][r][o] = dot(x_cls[b][r][:], Wp[o][:]) + bp[o]
// grid 768 = (b, 96 o-blocks of 16), 256 threads
// ============================================================================
__global__ void __launch_bounds__(256) k_out(const float* __restrict__ Wp,
                                             const float* __restrict__ bp,
                                             float* __restrict__ out) {
    int b = blockIdx.x / 96, oblk = blockIdx.x % 96;
    __shared__ float xcs[Rr * DIM];
    for (int i = threadIdx.x; i < Rr * DIM; i += 256)
        xcs[i] = g_xcls[(size_t)b * Rr * DIM + i];
    __syncthreads();
    int warp = threadIdx.x >> 5, lane = threadIdx.x & 31;
    #pragma unroll 1
    for (int i = 0; i < 2; i++) {
        int o = oblk * 16 + warp * 2 + i;
        const float* wrow = Wp + (size_t)o * DIM;
        float acc[8] = {0.f,0.f,0.f,0.f,0.f,0.f,0.f,0.f};
        for (int c = lane; c < DIM; c += 32) {
            float w = wrow[c];
            #pragma unroll
            for (int r = 0; r < 8; r++) acc[r] += w * xcs[r * DIM + c];
        }
        #pragma unroll
        for (int r = 0; r < 8; r++)
            #pragma unroll
            for (int off = 16; off > 0; off >>= 1)
                acc[r] += __shfl_xor_sync(0xffffffffu, acc[r], off);
        if (lane < 8)
            out[((size_t)b * Rr + lane) * DIM + o] = acc[lane] + bp[o];
    }
}

// ============================================================================
extern "C" void kernel_launch(void* const* d_in, const int* in_sizes, int n_in,
                              void* d_out, int out_size) {
    const float* x    = (const float*)d_in[0];
    const int*   mask = (const int*)d_in[1];
    const float* Wq   = (const float*)d_in[2];
    const float* Wk   = (const float*)d_in[3];
    const float* Wv   = (const float*)d_in[4];
    const float* Wp   = (const float*)d_in[5];
    const float* bp   = (const float*)d_in[6];
    float*       out  = (float*)d_out;

    cudaFuncSetAttribute(k_gemmS, cudaFuncAttributeMaxDynamicSharedMemorySize, SMEM_S);
    cudaFuncSetAttribute(k_gemmY, cudaFuncAttributeMaxDynamicSharedMemorySize, SMEM_Y);

    k_xh     <<<(int)(((size_t)Bc * Nn * DIM) / (256 * 8)), 256>>>(x);
    k_qg     <<<Bc * Hh, 256>>>(x, Wq, Wk);
    k_gemmS  <<<dim3(Nn / 256, JH / 64, Bc), 256, SMEM_S>>>(0);
    k_softmax<<<Bc * JH, 256>>>(mask);
    k_gemmY  <<<dim3(DIM / 256, JH / 64, Bc * KSPY), 256, SMEM_Y>>>(0);
    k_xcls   <<<Bc * Hh * 4, 256>>>(Wv);
    k_out    <<<Bc * 96, 256>>>(Wp, bp, out);
}

// round 16
// speedup vs baseline: 1.0093x; 1.0093x over previous
#include <cuda_runtime.h>
#include <cuda_fp16.h>
#include <mma.h>
#include <cstdint>

using namespace nvcuda;

// Problem constants
#define Bc   8
#define Nn   4096
#define DIM  1536
#define Hh   24
#define HD   64
#define Rr   8
#define JH   192
#define SCALE 0.125f
#define MASKW (Nn - Rr)

#define KSPY 2                  // split-K for Y (2048 per split)

// ---------------- scratch ----------------
__device__ __half g_Gh[Bc * JH * DIM];                  // [b][j][c] half
__device__ __half g_xh[(size_t)Bc * Nn * DIM];          // half copy of x
__device__ float  g_Sf[(size_t)Bc * JH * Nn];           // logits (fp32)
__device__ __half g_Sh[(size_t)Bc * JH * Nn];           // probs (half)
__device__ float  g_Yp[KSPY][Bc * JH * DIM];            // partial Y (fp32)
__device__ float  g_xcls[Bc * Rr * DIM];

// ---------------- cp.async helpers ----------------
__device__ __forceinline__ void cp16(void* s, const void* g) {
    uint32_t sa = (uint32_t)__cvta_generic_to_shared(s);
    asm volatile("cp.async.ca.shared.global [%0], [%1], 16;" :: "r"(sa), "l"(g));
}
__device__ __forceinline__ void cp_commit() { asm volatile("cp.async.commit_group;"); }
template<int N> __device__ __forceinline__ void cp_wait() {
    asm volatile("cp.async.wait_group %0;" :: "n"(N));
}

// ============================================================================
// K0: g_xh = half(x)  — vectorized convert, 8 floats/thread, no smem
// ============================================================================
__global__ void __launch_bounds__(256) k_xh(const float* __restrict__ x) {
    size_t i = ((size_t)blockIdx.x * 256 + threadIdx.x) * 8;
    float4 v0 = *(const float4*)&x[i];
    float4 v1 = *(const float4*)&x[i + 4];
    __half2 h[4];
    h[0] = __floats2half2_rn(v0.x, v0.y);
    h[1] = __floats2half2_rn(v0.z, v0.w);
    h[2] = __floats2half2_rn(v1.x, v1.y);
    h[3] = __floats2half2_rn(v1.z, v1.w);
    *(uint4*)&g_xh[i] = *(uint4*)h;
}

// ============================================================================
// K1 (fused): q = SCALE * x[:8] @ Wq_h^T ; G[j] = half(q @ Wk_h)
// grid 192 = (b,h), 256 threads
// ============================================================================
__global__ void __launch_bounds__(256) k_qg(const float* __restrict__ x,
                                            const float* __restrict__ Wq,
                                            const float* __restrict__ Wk) {
    int b = blockIdx.x / Hh, h = blockIdx.x % Hh;
    __shared__ float xs[Rr * DIM];
    const float* xb = x + (size_t)b * Nn * DIM;
    for (int i = threadIdx.x; i < Rr * DIM; i += 256) xs[i] = xb[i];
    __syncthreads();
    int warp = threadIdx.x >> 5, lane = threadIdx.x & 31;

    float qv[8];
    #pragma unroll 1
    for (int i = 0; i < 8; i++) {
        int d = warp * 8 + i;
        const float* wrow = Wq + (size_t)(h * HD + d) * DIM;
        float acc[8] = {0.f,0.f,0.f,0.f,0.f,0.f,0.f,0.f};
        for (int c = lane; c < DIM; c += 32) {
            float w = wrow[c];
            #pragma unroll
            for (int r = 0; r < 8; r++) acc[r] += w * xs[r * DIM + c];
        }
        #pragma unroll
        for (int r = 0; r < 8; r++)
            #pragma unroll
            for (int off = 16; off > 0; off >>= 1)
                acc[r] += __shfl_xor_sync(0xffffffffu, acc[r], off);
        qv[i] = (lane < 8) ? acc[lane] * SCALE : 0.f;
    }
    __syncthreads();
    if (lane < 8) {
        #pragma unroll
        for (int i = 0; i < 8; i++) xs[lane * HD + warp * 8 + i] = qv[i];
    }
    __syncthreads();

    float acc[6][8];
    #pragma unroll
    for (int cc = 0; cc < 6; cc++)
        #pragma unroll
        for (int r = 0; r < 8; r++) acc[cc][r] = 0.f;
    const float* wbase = Wk + (size_t)(h * HD) * DIM;
    #pragma unroll 4
    for (int d = 0; d < HD; d++) {
        #pragma unroll
        for (int cc = 0; cc < 6; cc++) {
            int c = cc * 256 + threadIdx.x;
            float w = wbase[(size_t)d * DIM + c];
            #pragma unroll
            for (int r = 0; r < 8; r++) acc[cc][r] += xs[r * HD + d] * w;
        }
    }
    #pragma unroll
    for (int cc = 0; cc < 6; cc++)
        #pragma unroll
        for (int r = 0; r < 8; r++)
            g_Gh[((size_t)b * JH + h * Rr + r) * DIM + cc * 256 + threadIdx.x] =
                __float2half_rn(acc[cc][r]);
}

// ============================================================================
// K2: S = Gh @ xh^T   (fp16 wmma m16n16k16)
// CTA 64(j) x 256(n), k-chunk 64, 2-stage cp.async. 8 warps 2x4, warp 32x64.
// grid (x=3 j-tiles, y=16 n-tiles, z=Bc): j fastest -> 3 CTAs share B in L2.
// 256 threads, dynamic smem 92KB
// ============================================================================
#define LD64  72                           // halves per k-chunk row (64 + 8 pad)
#define SA3   (64 * LD64)                  // 4608 halves / stage
#define SBS3  (256 * LD64)                 // 18432 halves / stage
#define SMEM_S ((SA3 + SBS3) * 2 * 2)      // 92160 B
#define NCS3  (DIM / 64)                   // 24 chunks
__global__ void __launch_bounds__(256) k_gemmS(int dummy) {
    extern __shared__ __half sm[];
    __half* As = sm;                        // 2 stages
    __half* Bs = sm + 2 * SA3;
    int b = blockIdx.z;
    int j0 = blockIdx.x * 64, n0 = blockIdx.y * 256;
    const __half* Ag = g_Gh + ((size_t)b * JH + j0) * DIM;
    const __half* Bg = g_xh + ((size_t)b * Nn + n0) * DIM;
    int tid = threadIdx.x;
    int warp = tid >> 5, wm = warp >> 2, wn = warp & 3;

    wmma::fragment<wmma::matrix_a, 16, 16, 16, __half, wmma::row_major> a0, a1;
    wmma::fragment<wmma::matrix_b, 16, 16, 16, __half, wmma::col_major> bf[4];
    wmma::fragment<wmma::accumulator, 16, 16, 16, float> c[2][4];
    #pragma unroll
    for (int mi = 0; mi < 2; mi++)
        #pragma unroll
        for (int ni = 0; ni < 4; ni++) wmma::fill_fragment(c[mi][ni], 0.f);

    auto prefetch = [&](int kc) {
        int s = kc & 1, k0 = kc << 6;
        #pragma unroll
        for (int p = 0; p < 2; p++) {
            int i = tid + p * 256; int row = i >> 3, seg = i & 7;
            cp16(&As[s * SA3 + row * LD64 + seg * 8], &Ag[(size_t)row * DIM + k0 + seg * 8]);
        }
        #pragma unroll
        for (int p = 0; p < 8; p++) {
            int i = tid + p * 256; int row = i >> 3, seg = i & 7;
            cp16(&Bs[s * SBS3 + row * LD64 + seg * 8], &Bg[(size_t)row * DIM + k0 + seg * 8]);
        }
        cp_commit();
    };
    prefetch(0);

    for (int kc = 0; kc < NCS3; kc++) {
        if (kc + 1 < NCS3) { prefetch(kc + 1); cp_wait<1>(); }
        else               { cp_wait<0>(); }
        __syncthreads();
        const __half* Ab = &As[(kc & 1) * SA3];
        const __half* Bb = &Bs[(kc & 1) * SBS3];
        #pragma unroll
        for (int kk = 0; kk < 64; kk += 16) {
            wmma::load_matrix_sync(a0, &Ab[(wm * 32) * LD64 + kk], LD64);
            wmma::load_matrix_sync(a1, &Ab[(wm * 32 + 16) * LD64 + kk], LD64);
            #pragma unroll
            for (int ni = 0; ni < 4; ni++)
                wmma::load_matrix_sync(bf[ni], &Bb[(wn * 64 + ni * 16) * LD64 + kk], LD64);
            #pragma unroll
            for (int ni = 0; ni < 4; ni++) {
                wmma::mma_sync(c[0][ni], a0, bf[ni], c[0][ni]);
                wmma::mma_sync(c[1][ni], a1, bf[ni], c[1][ni]);
            }
        }
        __syncthreads();
    }
    float* Sb = g_Sf + (size_t)b * JH * Nn;
    #pragma unroll
    for (int mi = 0; mi < 2; mi++)
        #pragma unroll
        for (int ni = 0; ni < 4; ni++)
            wmma::store_matrix_sync(&Sb[(size_t)(j0 + wm * 32 + mi * 16) * Nn + n0 + wn * 64 + ni * 16],
                                    c[mi][ni], Nn, wmma::mem_row_major);
}

// ============================================================================
// K3: masked softmax; writes half probs. grid 1536, 256 thr
// ============================================================================
__global__ void __launch_bounds__(256) k_softmax(const int* __restrict__ mask) {
    int bj = blockIdx.x;
    int b = bj / JH, j = bj % JH, r = j % Rr;
    const float* p0 = g_Sf + (size_t)bj * Nn;
    __half* row = g_Sh + (size_t)bj * Nn;
    const int* mrow = mask + ((size_t)b * Rr + r) * MASKW;
    int tid = threadIdx.x, warp = tid >> 5, lane = tid & 31;
    __shared__ float red[8];

    float v[16];
    float mx = -3.0e38f;
    #pragma unroll
    for (int i = 0; i < 16; i++) {
        int n = tid + (i << 8);
        bool valid = (n < Rr) ? (n == r) : (mrow[n - Rr] != 0);
        v[i] = valid ? p0[n] : -3.0e38f;
        mx = fmaxf(mx, v[i]);
    }
    #pragma unroll
    for (int off = 16; off > 0; off >>= 1) mx = fmaxf(mx, __shfl_xor_sync(0xffffffffu, mx, off));
    if (lane == 0) red[warp] = mx;
    __syncthreads();
    if (warp == 0) {
        float t = (lane < 8) ? red[lane] : -3.0e38f;
        #pragma unroll
        for (int off = 4; off > 0; off >>= 1) t = fmaxf(t, __shfl_xor_sync(0xffffffffu, t, off));
        if (lane == 0) red[0] = t;
    }
    __syncthreads();
    mx = red[0];
    __syncthreads();

    float sum = 0.f;
    #pragma unroll
    for (int i = 0; i < 16; i++) { v[i] = __expf(v[i] - mx); sum += v[i]; }
    #pragma unroll
    for (int off = 16; off > 0; off >>= 1) sum += __shfl_xor_sync(0xffffffffu, sum, off);
    if (lane == 0) red[warp] = sum;
    __syncthreads();
    if (warp == 0) {
        float t = (lane < 8) ? red[lane] : 0.f;
        #pragma unroll
        for (int off = 4; off > 0; off >>= 1) t += __shfl_xor_sync(0xffffffffu, t, off);
        if (lane == 0) red[0] = t;
    }
    __syncthreads();
    float inv = 1.f / red[0];
    #pragma unroll
    for (int i = 0; i < 16; i++)
        row[tid + (i << 8)] = __float2half_rn(v[i] * inv);
}

// ============================================================================
// K4: partial Y = Ph[:, slab] @ xh[slab, :]  (fp16 wmma m16n16k16, split-K 2)
// CTA 64(j) x 256(c), k-chunk 64, 2-stage cp.async. warp 32x64.
// grid (x=3 j-tiles, y=6 c-tiles, z=Bc*KSPY): j fastest -> B shared in L2.
// 256 threads, dynamic smem 86KB
// ============================================================================
#define LDBY3 264                          // halves per B row (256 + 8 pad)
#define SBY3  (64 * LDBY3)                 // 16896 halves / stage
#define SMEM_Y ((SA3 + SBY3) * 2 * 2)      // 86016 B
#define NCY3  (Nn / KSPY / 64)             // 32 chunks
__global__ void __launch_bounds__(256) k_gemmY(int dummy) {
    extern __shared__ __half sm[];
    __half* As = sm;
    __half* Bs = sm + 2 * SA3;
    int b = blockIdx.z >> 1, ks = blockIdx.z & 1;
    int koff = ks * (Nn / KSPY);
    int j0 = blockIdx.x * 64, c0 = blockIdx.y * 256;
    const __half* Ag = g_Sh + ((size_t)b * JH + j0) * Nn + koff;
    const __half* Bg = g_xh + ((size_t)b * Nn + koff) * DIM;
    int tid = threadIdx.x;
    int warp = tid >> 5, wm = warp >> 2, wn = warp & 3;

    wmma::fragment<wmma::matrix_a, 16, 16, 16, __half, wmma::row_major> a0, a1;
    wmma::fragment<wmma::matrix_b, 16, 16, 16, __half, wmma::row_major> bf[4];
    wmma::fragment<wmma::accumulator, 16, 16, 16, float> c[2][4];
    #pragma unroll
    for (int mi = 0; mi < 2; mi++)
        #pragma unroll
        for (int ni = 0; ni < 4; ni++) wmma::fill_fragment(c[mi][ni], 0.f);

    auto prefetch = [&](int kc) {
        int s = kc & 1, k0 = kc << 6;
        #pragma unroll
        for (int p = 0; p < 2; p++) {
            int i = tid + p * 256; int row = i >> 3, seg = i & 7;
            cp16(&As[s * SA3 + row * LD64 + seg * 8], &Ag[(size_t)row * Nn + k0 + seg * 8]);
        }
        #pragma unroll
        for (int p = 0; p < 8; p++) {
            int i = tid + p * 256; int row = i >> 5, seg = i & 31;
            cp16(&Bs[s * SBY3 + row * LDBY3 + seg * 8], &Bg[(size_t)(k0 + row) * DIM + c0 + seg * 8]);
        }
        cp_commit();
    };
    prefetch(0);

    for (int kc = 0; kc < NCY3; kc++) {
        if (kc + 1 < NCY3) { prefetch(kc + 1); cp_wait<1>(); }
        else               { cp_wait<0>(); }
        __syncthreads();
        const __half* Ab = &As[(kc & 1) * SA3];
        const __half* Bb = &Bs[(kc & 1) * SBY3];
        #pragma unroll
        for (int kk = 0; kk < 64; kk += 16) {
            wmma::load_matrix_sync(a0, &Ab[(wm * 32) * LD64 + kk], LD64);
            wmma::load_matrix_sync(a1, &Ab[(wm * 32 + 16) * LD64 + kk], LD64);
            #pragma unroll
            for (int ni = 0; ni < 4; ni++)
                wmma::load_matrix_sync(bf[ni], &Bb[kk * LDBY3 + wn * 64 + ni * 16], LDBY3);
            #pragma unroll
            for (int ni = 0; ni < 4; ni++) {
                wmma::mma_sync(c[0][ni], a0, bf[ni], c[0][ni]);
                wmma::mma_sync(c[1][ni], a1, bf[ni], c[1][ni]);
            }
        }
        __syncthreads();
    }
    float* Yb = g_Yp[ks] + (size_t)b * JH * DIM;
    #pragma unroll
    for (int mi = 0; mi < 2; mi++)
        #pragma unroll
        for (int ni = 0; ni < 4; ni++)
            wmma::store_matrix_sync(&Yb[(size_t)(j0 + wm * 32 + mi * 16) * DIM + c0 + wn * 64 + ni * 16],
                                    c[mi][ni], DIM, wmma::mem_row_major);
}

// ============================================================================
// K5a: reduce 2 Y partials + x_cls[b][r][e] = sum_c Y[b][h*8+r][c] * Wv[e][c]
// grid 384 = (b, h, ehalf), 256 threads; each block does 32 e-values
// ============================================================================
__global__ void __launch_bounds__(256) k_xcls(const float* __restrict__ Wv) {
    int bh = blockIdx.x >> 1, eh = blockIdx.x & 1;
    int b = bh / Hh, h = bh % Hh;
    __shared__ float Ys[Rr * DIM];
    size_t base = ((size_t)b * JH + h * Rr) * DIM;
    for (int i = threadIdx.x; i < Rr * DIM; i += 256)
        Ys[i] = g_Yp[0][base + i] + g_Yp[1][base + i];
    __syncthreads();
    int warp = threadIdx.x >> 5, lane = threadIdx.x & 31;
    #pragma unroll 1
    for (int i = 0; i < 4; i++) {
        int e = h * HD + eh * 32 + warp * 4 + i;
        const float* wrow = Wv + (size_t)e * DIM;
        float acc[8] = {0.f,0.f,0.f,0.f,0.f,0.f,0.f,0.f};
        for (int c = lane; c < DIM; c += 32) {
            float w = wrow[c];
            #pragma unroll
            for (int r = 0; r < 8; r++) acc[r] += w * Ys[r * DIM + c];
        }
        #pragma unroll
        for (int r = 0; r < 8; r++)
            #pragma unroll
            for (int off = 16; off > 0; off >>= 1)
                acc[r] += __shfl_xor_sync(0xffffffffu, acc[r], off);
        if (lane < 8)
            g_xcls[((size_t)b * Rr + lane) * DIM + e] = acc[lane];
    }
}

// ============================================================================
// K5b: out[b][r][o] = dot(x_cls[b][r][:], Wp[o][:]) + bp[o]
// grid 384 = (b, 48 o-blocks of 32), 256 threads
// ============================================================================
__global__ void __launch_bounds__(256) k_out(const float* __restrict__ Wp,
                                             const float* __restrict__ bp,
                                             float* __restrict__ out) {
    int b = blockIdx.x / 48, oblk = blockIdx.x % 48;
    __shared__ float xcs[Rr * DIM];
    for (int i = threadIdx.x; i < Rr * DIM; i += 256)
        xcs[i] = g_xcls[(size_t)b * Rr * DIM + i];
    __syncthreads();
    int warp = threadIdx.x >> 5, lane = threadIdx.x & 31;
    #pragma unroll 1
    for (int i = 0; i < 4; i++) {
        int o = oblk * 32 + warp * 4 + i;
        const float* wrow = Wp + (size_t)o * DIM;
        float acc[8] = {0.f,0.f,0.f,0.f,0.f,0.f,0.f,0.f};
        for (int c = lane; c < DIM; c += 32) {
            float w = wrow[c];
            #pragma unroll
            for (int r = 0; r < 8; r++) acc[r] += w * xcs[r * DIM + c];
        }
        #pragma unroll
        for (int r = 0; r < 8; r++)
            #pragma unroll
            for (int off = 16; off > 0; off >>= 1)
                acc[r] += __shfl_xor_sync(0xffffffffu, acc[r], off);
        if (lane < 8)
            out[((size_t)b * Rr + lane) * DIM + o] = acc[lane] + bp[o];
    }
}

// ============================================================================
extern "C" void kernel_launch(void* const* d_in, const int* in_sizes, int n_in,
                              void* d_out, int out_size) {
    const float* x    = (const float*)d_in[0];
    const int*   mask = (const int*)d_in[1];
    const float* Wq   = (const float*)d_in[2];
    const float* Wk   = (const float*)d_in[3];
    const float* Wv   = (const float*)d_in[4];
    const float* Wp   = (const float*)d_in[5];
    const float* bp   = (const float*)d_in[6];
    float*       out  = (float*)d_out;

    cudaFuncSetAttribute(k_gemmS, cudaFuncAttributeMaxDynamicSharedMemorySize, SMEM_S);
    cudaFuncSetAttribute(k_gemmY, cudaFuncAttributeMaxDynamicSharedMemorySize, SMEM_Y);

    k_xh     <<<(int)(((size_t)Bc * Nn * DIM) / (256 * 8)), 256>>>(x);
    k_qg     <<<Bc * Hh, 256>>>(x, Wq, Wk);
    k_gemmS  <<<dim3(JH / 64, Nn / 256, Bc), 256, SMEM_S>>>(0);
    k_softmax<<<Bc * JH, 256>>>(mask);
    k_gemmY  <<<dim3(JH / 64, DIM / 256, Bc * KSPY), 256, SMEM_Y>>>(0);
    k_xcls   <<<Bc * Hh * 2, 256>>>(Wv);
    k_out    <<<Bc * 48, 256>>>(Wp, bp, out);
}